// round 7
// baseline (speedup 1.0000x reference)
#include <cuda_runtime.h>
#include <math.h>

#define B_   4
#define N_   16384
#define S_   4096
#define K_   32
#define CIN_ 16
#define EPS_ 1e-5f

// ---------------- device scratch (no allocations allowed) ----------------
__device__ int g_knn[B_ * S_ * K_];

// packed folded weights: w0t[32*20] | fb0[32] | w1t[32*32] | fb1[32] | w2t[64*32] | fb2[64]
#define OFF_W0  0
#define OFF_FB0 (32 * 20)
#define OFF_W1  (OFF_FB0 + 32)
#define OFF_FB1 (OFF_W1 + 32 * 32)
#define OFF_W2  (OFF_FB1 + 32)
#define OFF_FB2 (OFF_W2 + 64 * 32)
#define WTOT    (OFF_FB2 + 64)   // 3840 floats
__device__ float g_w[WTOT];

// ---------------- BN-fold prep (one tiny block) ----------------
__global__ void prep_kernel(
    const float* __restrict__ w0, const float* __restrict__ b0, const float* __restrict__ g0,
    const float* __restrict__ bt0, const float* __restrict__ rm0, const float* __restrict__ rv0,
    const float* __restrict__ w1, const float* __restrict__ b1, const float* __restrict__ g1,
    const float* __restrict__ bt1, const float* __restrict__ rm1, const float* __restrict__ rv1,
    const float* __restrict__ w2, const float* __restrict__ b2, const float* __restrict__ g2,
    const float* __restrict__ bt2, const float* __restrict__ rm2, const float* __restrict__ rv2)
{
    int t = threadIdx.x;
    if (t < 32) {
        float sc = g0[t] / sqrtf(rv0[t] + EPS_);
        g_w[OFF_FB0 + t] = (b0[t] - rm0[t]) * sc + bt0[t];
        for (int c = 0; c < 19; ++c) g_w[OFF_W0 + t * 20 + c] = w0[c * 32 + t] * sc;
        g_w[OFF_W0 + t * 20 + 19] = 0.f;

        float sc1 = g1[t] / sqrtf(rv1[t] + EPS_);
        g_w[OFF_FB1 + t] = (b1[t] - rm1[t]) * sc1 + bt1[t];
        for (int c = 0; c < 32; ++c) g_w[OFF_W1 + t * 32 + c] = w1[c * 32 + t] * sc1;
    }
    if (t < 64) {
        float sc2 = g2[t] / sqrtf(rv2[t] + EPS_);
        g_w[OFF_FB2 + t] = (b2[t] - rm2[t]) * sc2 + bt2[t];
        for (int c = 0; c < 32; ++c) g_w[OFF_W2 + t * 32 + c] = w2[c * 64 + t] * sc2;
    }
}

// ---------------- KNN: warp-cooperative top-32, 4 queries per warp ----------------
// Distances compared as int bits (monotone for >=0 floats; near-zero negative
// rounding artifacts map to "smallest" = correct set membership). Top-32 list
// distributed across the warp: lane L owns entry L. Inserts are warp-uniform:
// ballot -> shfl candidate -> victim ballot -> predicated replace ->
// __reduce_max_sync. ~10 issue slots per insert, fully branch-uniform.
#define TILE_PTS 2048

__global__ __launch_bounds__(256) void knn_kernel(
    const float* __restrict__ xyz, const int* __restrict__ sidx)
{
    __shared__ float4 tile[TILE_PTS];   // 32 KB

    const int b    = blockIdx.y;
    const int lane = threadIdx.x & 31;
    const int warp = threadIdx.x >> 5;
    const float* xb = xyz + (size_t)b * N_ * 3;

    const int qbase = (blockIdx.x * 8 + warp) * 4;   // 4 consecutive queries
    float m0[4], m1[4], m2[4], qq[4];
    int ed[4], ei[4], kmax[4];
#pragma unroll
    for (int q = 0; q < 4; ++q) {
        int si = sidx[b * S_ + qbase + q];
        float qx = xb[si * 3 + 0], qy = xb[si * 3 + 1], qz = xb[si * 3 + 2];
        qq[q] = qx * qx + qy * qy + qz * qz;
        m0[q] = -2.f * qx; m1[q] = -2.f * qy; m2[q] = -2.f * qz;
        ed[q] = 0x7f7fffff; ei[q] = 0; kmax[q] = 0x7f7fffff;
    }

    for (int t0 = 0; t0 < N_; t0 += TILE_PTS) {
        __syncthreads();
        for (int i = threadIdx.x; i < TILE_PTS; i += 256) {
            int p = t0 + i;
            float x = xb[p * 3 + 0], y = xb[p * 3 + 1], z = xb[p * 3 + 2];
            tile[i] = make_float4(x, y, z, x * x + y * y + z * z);
        }
        __syncthreads();

        int j0 = 0;
        if (t0 == 0) {
            // seed the distributed lists with the first 32 points (lane = point)
            float4 pt = tile[lane];
#pragma unroll
            for (int q = 0; q < 4; ++q) {
                float d = fmaf(m0[q], pt.x, fmaf(m1[q], pt.y,
                          fmaf(m2[q], pt.z, qq[q] + pt.w)));
                ed[q] = __float_as_int(d);
                ei[q] = lane;
                kmax[q] = __reduce_max_sync(0xffffffffu, ed[q]);
            }
            j0 = 1;
        }

        for (int j = j0; j < TILE_PTS / 32; ++j) {
            const int li = (j << 5) | lane;
            const float4 pt = tile[li];
            const int pidx = t0 + li;
            int dint[4];
            bool p0, p1, p2, p3;
#pragma unroll
            for (int q = 0; q < 4; ++q) {
                float d = fmaf(m0[q], pt.x, fmaf(m1[q], pt.y,
                          fmaf(m2[q], pt.z, qq[q] + pt.w)));
                dint[q] = __float_as_int(d);
            }
            p0 = dint[0] < kmax[0]; p1 = dint[1] < kmax[1];
            p2 = dint[2] < kmax[2]; p3 = dint[3] < kmax[3];

            if (__ballot_sync(0xffffffffu, p0 | p1 | p2 | p3)) {
#pragma unroll
                for (int q = 0; q < 4; ++q) {
                    unsigned mask = __ballot_sync(0xffffffffu, dint[q] < kmax[q]);
                    while (mask) {
                        int src = __ffs(mask) - 1; mask &= mask - 1;
                        int cd = __shfl_sync(0xffffffffu, dint[q], src);
                        int ci = __shfl_sync(0xffffffffu, pidx, src);
                        if (cd < kmax[q]) {   // uniform: kmax may have tightened
                            unsigned vm = __ballot_sync(0xffffffffu, ed[q] == kmax[q]);
                            int victim = __ffs(vm) - 1;
                            if (lane == victim) { ed[q] = cd; ei[q] = ci; }
                            kmax[q] = __reduce_max_sync(0xffffffffu, ed[q]);
                        }
                    }
                }
            }
        }
    }

#pragma unroll
    for (int q = 0; q < 4; ++q)
        g_knn[(size_t)(b * S_ + qbase + q) * K_ + lane] = ei[q];
}

// ---------------- fused gather + MLP(3 layers, BN folded) + max-pool ----------------
__global__ __launch_bounds__(256) void mlp_kernel(
    const float* __restrict__ xyz, const float* __restrict__ feat,
    const int* __restrict__ sidx, float* __restrict__ out)
{
    __shared__ __align__(16) float sw[WTOT];
    for (int i = threadIdx.x; i < WTOT; i += 256) sw[i] = g_w[i];
    __syncthreads();

    const int warp = threadIdx.x >> 5, lane = threadIdx.x & 31;
    const int q = blockIdx.x * 8 + warp;    // one warp per query, lane = neighbor
    const int b = q >> 12;                  // S = 4096
    const float* xb  = xyz  + (size_t)b * N_ * 3;
    const float* fbp = feat + (size_t)b * N_ * CIN_;

    const int si = sidx[q];
    const float qx = xb[si * 3 + 0], qy = xb[si * 3 + 1], qz = xb[si * 3 + 2];

    const int ni = g_knn[q * K_ + lane];
    float x[20];
    x[0] = xb[ni * 3 + 0] - qx;
    x[1] = xb[ni * 3 + 1] - qy;
    x[2] = xb[ni * 3 + 2] - qz;
    const float4* f4 = (const float4*)(fbp + (size_t)ni * CIN_);
    float4 f0 = f4[0], f1 = f4[1], f2 = f4[2], f3 = f4[3];
    x[3]  = f0.x; x[4]  = f0.y; x[5]  = f0.z; x[6]  = f0.w;
    x[7]  = f1.x; x[8]  = f1.y; x[9]  = f1.z; x[10] = f1.w;
    x[11] = f2.x; x[12] = f2.y; x[13] = f2.z; x[14] = f2.w;
    x[15] = f3.x; x[16] = f3.y; x[17] = f3.z; x[18] = f3.w;
    x[19] = 0.f;

    float h1[32];
#pragma unroll
    for (int d = 0; d < 32; ++d) {
        const float4* wp = (const float4*)&sw[OFF_W0 + d * 20];
        float acc = sw[OFF_FB0 + d];
        float4 w;
        w = wp[0]; acc = fmaf(x[0],  w.x, acc); acc = fmaf(x[1],  w.y, acc);
                   acc = fmaf(x[2],  w.z, acc); acc = fmaf(x[3],  w.w, acc);
        w = wp[1]; acc = fmaf(x[4],  w.x, acc); acc = fmaf(x[5],  w.y, acc);
                   acc = fmaf(x[6],  w.z, acc); acc = fmaf(x[7],  w.w, acc);
        w = wp[2]; acc = fmaf(x[8],  w.x, acc); acc = fmaf(x[9],  w.y, acc);
                   acc = fmaf(x[10], w.z, acc); acc = fmaf(x[11], w.w, acc);
        w = wp[3]; acc = fmaf(x[12], w.x, acc); acc = fmaf(x[13], w.y, acc);
                   acc = fmaf(x[14], w.z, acc); acc = fmaf(x[15], w.w, acc);
        w = wp[4]; acc = fmaf(x[16], w.x, acc); acc = fmaf(x[17], w.y, acc);
                   acc = fmaf(x[18], w.z, acc); acc = fmaf(x[19], w.w, acc);
        h1[d] = fmaxf(acc, 0.f);
    }

    float h2[32];
#pragma unroll
    for (int d = 0; d < 32; ++d) {
        const float4* wp = (const float4*)&sw[OFF_W1 + d * 32];
        float acc = sw[OFF_FB1 + d];
#pragma unroll
        for (int c4 = 0; c4 < 8; ++c4) {
            float4 w = wp[c4];
            acc = fmaf(h1[c4 * 4 + 0], w.x, acc);
            acc = fmaf(h1[c4 * 4 + 1], w.y, acc);
            acc = fmaf(h1[c4 * 4 + 2], w.z, acc);
            acc = fmaf(h1[c4 * 4 + 3], w.w, acc);
        }
        h2[d] = fmaxf(acc, 0.f);
    }

    float my0 = 0.f, my1 = 0.f;
#pragma unroll
    for (int d0 = 0; d0 < 64; d0 += 8) {
        float o[8];
#pragma unroll
        for (int j = 0; j < 8; ++j) {
            int d = d0 + j;
            const float4* wp = (const float4*)&sw[OFF_W2 + d * 32];
            float acc = sw[OFF_FB2 + d];
#pragma unroll
            for (int c4 = 0; c4 < 8; ++c4) {
                float4 w = wp[c4];
                acc = fmaf(h2[c4 * 4 + 0], w.x, acc);
                acc = fmaf(h2[c4 * 4 + 1], w.y, acc);
                acc = fmaf(h2[c4 * 4 + 2], w.z, acc);
                acc = fmaf(h2[c4 * 4 + 3], w.w, acc);
            }
            o[j] = fmaxf(acc, 0.f);
        }
#pragma unroll
        for (int j = 0; j < 8; ++j) {
            float m = o[j];
#pragma unroll
            for (int off = 16; off >= 1; off >>= 1)
                m = fmaxf(m, __shfl_xor_sync(0xffffffffu, m, off));
            int d = d0 + j;
            if ((d & 31) == lane) { if (d < 32) my0 = m; else my1 = m; }
        }
    }

    // output layout: [new_xyz | new_feature | sample_idx(as float)]
    float* fo = out + (size_t)B_ * S_ * 3;
    fo[(size_t)q * 64 + lane]      = my0;
    fo[(size_t)q * 64 + 32 + lane] = my1;
    if (lane == 0) {
        out[q * 3 + 0] = qx; out[q * 3 + 1] = qy; out[q * 3 + 2] = qz;
        out[(size_t)B_ * S_ * 3 + (size_t)B_ * S_ * 64 + q] = (float)si;
    }
}

// ---------------- launch ----------------
extern "C" void kernel_launch(void* const* d_in, const int* in_sizes, int n_in,
                              void* d_out, int out_size)
{
    const float* xyz     = (const float*)d_in[0];
    const float* feature = (const float*)d_in[1];
    const int*   sample  = (const int*)d_in[2];

    prep_kernel<<<1, 64>>>(
        (const float*)d_in[3],  (const float*)d_in[4],  (const float*)d_in[5],
        (const float*)d_in[6],  (const float*)d_in[7],  (const float*)d_in[8],
        (const float*)d_in[9],  (const float*)d_in[10], (const float*)d_in[11],
        (const float*)d_in[12], (const float*)d_in[13], (const float*)d_in[14],
        (const float*)d_in[15], (const float*)d_in[16], (const float*)d_in[17],
        (const float*)d_in[18], (const float*)d_in[19], (const float*)d_in[20]);

    dim3 kg(S_ / 32, B_);
    knn_kernel<<<kg, 256>>>(xyz, sample);

    mlp_kernel<<<(B_ * S_) / 8, 256>>>(xyz, feature, sample, (float*)d_out);
}

// round 12
// speedup vs baseline: 1.0695x; 1.0695x over previous
#include <cuda_runtime.h>
#include <math.h>

#define B_   4
#define N_   16384
#define S_   4096
#define K_   32
#define CIN_ 16
#define EPS_ 1e-5f

typedef unsigned long long u64;

// packed f32x2 ops (sm_100+): the only route to FFMA2 SASS
#define FMA2(d, a, b, c) \
    asm("fma.rn.f32x2 %0, %1, %2, %3;" : "=l"(d) : "l"(a), "l"(b), "l"(c))
#define DUP2(d, f) \
    asm("mov.b64 %0, {%1, %1};" : "=l"(d) : "r"(__float_as_int(f)))
#define UNPK2(lo, hi, v) \
    asm("mov.b64 {%0, %1}, %2;" : "=r"(lo), "=r"(hi) : "l"(v))

// ---------------- device scratch (no allocations allowed) ----------------
__device__ int g_knn[B_ * S_ * K_];

// pair-interleaved folded weights:
//  w0p: 16 pairs x 20c x2 | fb0[32] | w1p: 16x32x2 | fb1[32] | w2p: 32x32x2 | fb2[64]
#define OFF_W0  0
#define OFF_FB0 640
#define OFF_W1  672
#define OFF_FB1 1696
#define OFF_W2  1728
#define OFF_FB2 3776
#define WTOT    3840
__device__ float g_w[WTOT];

// ---------------- BN-fold prep (parallel, pair-interleaved output) ----------------
__global__ __launch_bounds__(256) void prep_kernel(
    const float* __restrict__ w0, const float* __restrict__ b0, const float* __restrict__ g0,
    const float* __restrict__ bt0, const float* __restrict__ rm0, const float* __restrict__ rv0,
    const float* __restrict__ w1, const float* __restrict__ b1, const float* __restrict__ g1,
    const float* __restrict__ bt1, const float* __restrict__ rm1, const float* __restrict__ rv1,
    const float* __restrict__ w2, const float* __restrict__ b2, const float* __restrict__ g2,
    const float* __restrict__ bt2, const float* __restrict__ rm2, const float* __restrict__ rv2)
{
    int t = threadIdx.x;
    if (t < 32) {
        float sc = g0[t] / sqrtf(rv0[t] + EPS_);
        g_w[OFF_FB0 + t] = (b0[t] - rm0[t]) * sc + bt0[t];
        float sc1 = g1[t] / sqrtf(rv1[t] + EPS_);
        g_w[OFF_FB1 + t] = (b1[t] - rm1[t]) * sc1 + bt1[t];
    }
    if (t < 64) {
        float sc2 = g2[t] / sqrtf(rv2[t] + EPS_);
        g_w[OFF_FB2 + t] = (b2[t] - rm2[t]) * sc2 + bt2[t];
    }
    for (int idx = t; idx < 16 * 20; idx += 256) {         // layer0 pairs
        int p = idx / 20, c = idx % 20;
        int d0 = 2 * p, d1 = d0 + 1;
        float s0 = g0[d0] / sqrtf(rv0[d0] + EPS_);
        float s1 = g0[d1] / sqrtf(rv0[d1] + EPS_);
        g_w[OFF_W0 + p * 40 + 2 * c + 0] = (c < 19) ? w0[c * 32 + d0] * s0 : 0.f;
        g_w[OFF_W0 + p * 40 + 2 * c + 1] = (c < 19) ? w0[c * 32 + d1] * s1 : 0.f;
    }
    for (int idx = t; idx < 16 * 32; idx += 256) {         // layer1 pairs
        int p = idx / 32, c = idx % 32;
        int d0 = 2 * p, d1 = d0 + 1;
        float s0 = g1[d0] / sqrtf(rv1[d0] + EPS_);
        float s1 = g1[d1] / sqrtf(rv1[d1] + EPS_);
        g_w[OFF_W1 + p * 64 + 2 * c + 0] = w1[c * 32 + d0] * s0;
        g_w[OFF_W1 + p * 64 + 2 * c + 1] = w1[c * 32 + d1] * s1;
    }
    for (int idx = t; idx < 32 * 32; idx += 256) {         // layer2 pairs
        int p = idx / 32, c = idx % 32;
        int d0 = 2 * p, d1 = d0 + 1;
        float s0 = g2[d0] / sqrtf(rv2[d0] + EPS_);
        float s1 = g2[d1] / sqrtf(rv2[d1] + EPS_);
        g_w[OFF_W2 + p * 64 + 2 * c + 0] = w2[c * 64 + d0] * s0;
        g_w[OFF_W2 + p * 64 + 2 * c + 1] = w2[c * 64 + d1] * s1;
    }
}

// ---------------- KNN: warp-cooperative top-32, 4 queries per warp ----------------
// Keys are int bits of d computed EXACTLY as in the passing Round-7 kernel:
// d = fma(m0,x, fma(m1,y, fma(m2,z, qq + |p|^2))) — rounding is relative to
// |d| itself (boundary distances ~0.1-1), not an inflated offset. The +64-shift
// variant quantized keys at magnitude ~64 and pushed rel_err to 2e-3 (Round 10).
#define TILE_PTS 2048

__global__ __launch_bounds__(256) void knn_kernel(
    const float* __restrict__ xyz, const int* __restrict__ sidx)
{
    __shared__ float4 tile[TILE_PTS];   // 32 KB

    const int b    = blockIdx.y;
    const int lane = threadIdx.x & 31;
    const int warp = threadIdx.x >> 5;
    const float* xb = xyz + (size_t)b * N_ * 3;

    const int qbase = (blockIdx.x * 8 + warp) * 4;   // 4 consecutive queries
    float m0[4], m1[4], m2[4], qq[4];
    int ed[4], ei[4], kmax[4];
#pragma unroll
    for (int q = 0; q < 4; ++q) {
        int si = sidx[b * S_ + qbase + q];
        float qx = xb[si * 3 + 0], qy = xb[si * 3 + 1], qz = xb[si * 3 + 2];
        qq[q] = qx * qx + qy * qy + qz * qz;
        m0[q] = -2.f * qx; m1[q] = -2.f * qy; m2[q] = -2.f * qz;
        ed[q] = 0x7f7fffff; ei[q] = 0; kmax[q] = 0x7f7fffff;
    }

    for (int t0 = 0; t0 < N_; t0 += TILE_PTS) {
        __syncthreads();
        for (int i = threadIdx.x; i < TILE_PTS; i += 256) {
            int p = t0 + i;
            float x = xb[p * 3 + 0], y = xb[p * 3 + 1], z = xb[p * 3 + 2];
            tile[i] = make_float4(x, y, z, x * x + y * y + z * z);
        }
        __syncthreads();

        int j0 = 0;
        if (t0 == 0) {
            // seed the distributed lists with the first 32 points (lane = point)
            float4 pt = tile[lane];
#pragma unroll
            for (int q = 0; q < 4; ++q) {
                float d = fmaf(m0[q], pt.x, fmaf(m1[q], pt.y,
                          fmaf(m2[q], pt.z, qq[q] + pt.w)));
                ed[q] = __float_as_int(d);
                ei[q] = lane;
                kmax[q] = __reduce_max_sync(0xffffffffu, ed[q]);
            }
            j0 = 1;
        }

        for (int j = j0; j < TILE_PTS / 32; ++j) {
            const int li = (j << 5) | lane;
            const float4 pt = tile[li];
            const int pidx = t0 + li;
            int dint[4];
#pragma unroll
            for (int q = 0; q < 4; ++q) {
                float d = fmaf(m0[q], pt.x, fmaf(m1[q], pt.y,
                          fmaf(m2[q], pt.z, qq[q] + pt.w)));
                dint[q] = __float_as_int(d);
            }
            bool p0 = dint[0] < kmax[0], p1 = dint[1] < kmax[1];
            bool p2 = dint[2] < kmax[2], p3 = dint[3] < kmax[3];

            if (__ballot_sync(0xffffffffu, p0 | p1 | p2 | p3)) {
#pragma unroll
                for (int q = 0; q < 4; ++q) {
                    unsigned mask = __ballot_sync(0xffffffffu, dint[q] < kmax[q]);
                    while (mask) {
                        int src = __ffs(mask) - 1; mask &= mask - 1;
                        int cd = __shfl_sync(0xffffffffu, dint[q], src);
                        int ci = __shfl_sync(0xffffffffu, pidx, src);
                        if (cd < kmax[q]) {   // uniform: kmax may have tightened
                            unsigned vm = __ballot_sync(0xffffffffu, ed[q] == kmax[q]);
                            int victim = __ffs(vm) - 1;
                            if (lane == victim) { ed[q] = cd; ei[q] = ci; }
                            kmax[q] = __reduce_max_sync(0xffffffffu, ed[q]);
                        }
                    }
                }
            }
        }
    }

#pragma unroll
    for (int q = 0; q < 4; ++q)
        g_knn[(size_t)(b * S_ + qbase + q) * K_ + lane] = ei[q];
}

// ------- fused gather + MLP (f32x2-packed, BN folded) + redux max-pool -------
__global__ __launch_bounds__(256) void mlp_kernel(
    const float* __restrict__ xyz, const float* __restrict__ feat,
    const int* __restrict__ sidx, float* __restrict__ out)
{
    __shared__ __align__(16) float sw[WTOT];
    for (int i = threadIdx.x; i < WTOT; i += 256) sw[i] = g_w[i];
    __syncthreads();

    const int warp = threadIdx.x >> 5, lane = threadIdx.x & 31;
    const int q = blockIdx.x * 8 + warp;    // one warp per query, lane = neighbor
    const int b = q >> 12;                  // S = 4096
    const float* xb  = xyz  + (size_t)b * N_ * 3;
    const float* fbp = feat + (size_t)b * N_ * CIN_;

    const int si = sidx[q];
    const float qx = xb[si * 3 + 0], qy = xb[si * 3 + 1], qz = xb[si * 3 + 2];

    const int ni = g_knn[q * K_ + lane];
    float x[20];
    x[0] = xb[ni * 3 + 0] - qx;
    x[1] = xb[ni * 3 + 1] - qy;
    x[2] = xb[ni * 3 + 2] - qz;
    const float4* f4 = (const float4*)(fbp + (size_t)ni * CIN_);
    float4 f0 = f4[0], f1 = f4[1], f2 = f4[2], f3 = f4[3];
    x[3]  = f0.x; x[4]  = f0.y; x[5]  = f0.z; x[6]  = f0.w;
    x[7]  = f1.x; x[8]  = f1.y; x[9]  = f1.z; x[10] = f1.w;
    x[11] = f2.x; x[12] = f2.y; x[13] = f2.z; x[14] = f2.w;
    x[15] = f3.x; x[16] = f3.y; x[17] = f3.z; x[18] = f3.w;
    x[19] = 0.f;

    u64 x2[20];
#pragma unroll
    for (int c = 0; c < 20; ++c) DUP2(x2[c], x[c]);

    u64 h1_2[32];
#pragma unroll
    for (int p = 0; p < 16; ++p) {
        u64 acc = *(const u64*)&sw[OFF_FB0 + 2 * p];
        const ulonglong2* wp = (const ulonglong2*)&sw[OFF_W0 + p * 40];
#pragma unroll
        for (int c2 = 0; c2 < 10; ++c2) {
            ulonglong2 w = wp[c2];
            FMA2(acc, x2[2 * c2],     w.x, acc);
            FMA2(acc, x2[2 * c2 + 1], w.y, acc);
        }
        unsigned lo, hi; UNPK2(lo, hi, acc);
        DUP2(h1_2[2 * p],     fmaxf(__uint_as_float(lo), 0.f));
        DUP2(h1_2[2 * p + 1], fmaxf(__uint_as_float(hi), 0.f));
    }

    u64 h2_2[32];
#pragma unroll
    for (int p = 0; p < 16; ++p) {
        u64 acc = *(const u64*)&sw[OFF_FB1 + 2 * p];
        const ulonglong2* wp = (const ulonglong2*)&sw[OFF_W1 + p * 64];
#pragma unroll
        for (int c2 = 0; c2 < 16; ++c2) {
            ulonglong2 w = wp[c2];
            FMA2(acc, h1_2[2 * c2],     w.x, acc);
            FMA2(acc, h1_2[2 * c2 + 1], w.y, acc);
        }
        unsigned lo, hi; UNPK2(lo, hi, acc);
        DUP2(h2_2[2 * p],     fmaxf(__uint_as_float(lo), 0.f));
        DUP2(h2_2[2 * p + 1], fmaxf(__uint_as_float(hi), 0.f));
    }

    float my0 = 0.f, my1 = 0.f;
#pragma unroll
    for (int p = 0; p < 32; ++p) {
        u64 acc = *(const u64*)&sw[OFF_FB2 + 2 * p];
        const ulonglong2* wp = (const ulonglong2*)&sw[OFF_W2 + p * 64];
#pragma unroll
        for (int c2 = 0; c2 < 16; ++c2) {
            ulonglong2 w = wp[c2];
            FMA2(acc, h2_2[2 * c2],     w.x, acc);
            FMA2(acc, h2_2[2 * c2 + 1], w.y, acc);
        }
        unsigned lo, hi; UNPK2(lo, hi, acc);
        // post-ReLU values are >= 0, so int-bit max == float max
        int r0 = __reduce_max_sync(0xffffffffu,
                     __float_as_int(fmaxf(__uint_as_float(lo), 0.f)));
        int r1 = __reduce_max_sync(0xffffffffu,
                     __float_as_int(fmaxf(__uint_as_float(hi), 0.f)));
        int d0 = 2 * p;
        if (d0 < 32) {
            if (lane == d0)      my0 = __int_as_float(r0);
            if (lane == d0 + 1)  my0 = __int_as_float(r1);
        } else {
            if (lane == d0 - 32) my1 = __int_as_float(r0);
            if (lane == d0 - 31) my1 = __int_as_float(r1);
        }
    }

    // output layout: [new_xyz | new_feature | sample_idx(as float)]
    float* fo = out + (size_t)B_ * S_ * 3;
    fo[(size_t)q * 64 + lane]      = my0;
    fo[(size_t)q * 64 + 32 + lane] = my1;
    if (lane == 0) {
        out[q * 3 + 0] = qx; out[q * 3 + 1] = qy; out[q * 3 + 2] = qz;
        out[(size_t)B_ * S_ * 3 + (size_t)B_ * S_ * 64 + q] = (float)si;
    }
}

// ---------------- launch (knn first so the ncu capture slot lands on it) ----------------
extern "C" void kernel_launch(void* const* d_in, const int* in_sizes, int n_in,
                              void* d_out, int out_size)
{
    const float* xyz     = (const float*)d_in[0];
    const float* feature = (const float*)d_in[1];
    const int*   sample  = (const int*)d_in[2];

    dim3 kg(S_ / 32, B_);
    knn_kernel<<<kg, 256>>>(xyz, sample);

    prep_kernel<<<1, 256>>>(
        (const float*)d_in[3],  (const float*)d_in[4],  (const float*)d_in[5],
        (const float*)d_in[6],  (const float*)d_in[7],  (const float*)d_in[8],
        (const float*)d_in[9],  (const float*)d_in[10], (const float*)d_in[11],
        (const float*)d_in[12], (const float*)d_in[13], (const float*)d_in[14],
        (const float*)d_in[15], (const float*)d_in[16], (const float*)d_in[17],
        (const float*)d_in[18], (const float*)d_in[19], (const float*)d_in[20]);

    mlp_kernel<<<(B_ * S_) / 8, 256>>>(xyz, feature, sample, (float*)d_out);
}